// round 5
// baseline (speedup 1.0000x reference)
#include <cuda_runtime.h>
#include <cuda_fp16.h>
#include <cstdint>
#include <cstddef>

#define NPTS 300000

static constexpr int kV0 = 60000, kV1 = 30000, kV2 = 15000, kV3 = 120000;
static constexpr int kTOTV = kV0 + kV1 + kV2 + kV3;            // 225000
static constexpr int kOFF0 = 0, kOFF1 = 60000, kOFF2 = 90000, kOFF3 = 105000;
static constexpr int kVIN = kV0 + kV1 + kV2;                   // 105000

// ---------------- scratch (static device globals; no allocation) -------------
__device__ float4 g_sums[kTOTV];            // per-voxel point sums (x,y,z,w)
__device__ float  g_counts[kTOTV];          // per-voxel counts
__device__ int    g_offsets[kTOTV];         // per-scale exclusive scan of counts
__device__ int    g_cursor[kTOTV];          // fill cursors
__device__ int    g_plist[4 * NPTS];        // CSR point lists, segmented per scale
__device__ __half g_sf1[(size_t)NPTS * 192];   // [N, 3*64] AVFE sf features (half)
__device__ __half g_vmax[(size_t)kVIN * 64];   // per-voxel max of sf, scales 0-2
__device__ float  g_sf2[(size_t)NPTS * 128];   // [N,128] AVFEO sf before segmax
__device__ __half g_wt[128 * 384];          // W_pt2 transposed to [n][k], half

__device__ __forceinline__ float relu(float x) { return fmaxf(x, 0.f); }

__device__ __forceinline__ uint32_t smem_u32(const void* p) {
    uint32_t a;
    asm("{ .reg .u64 t; cvta.to.shared.u64 t, %1; cvt.u32.u64 %0, t; }"
        : "=r"(a) : "l"(p));
    return a;
}

__device__ __forceinline__ void mma16816(float* c, const uint32_t* a,
                                         uint32_t b0, uint32_t b1) {
    asm volatile(
        "mma.sync.aligned.m16n8k16.row.col.f32.f16.f16.f32 "
        "{%0,%1,%2,%3}, {%4,%5,%6,%7}, {%8,%9}, {%0,%1,%2,%3};"
        : "+f"(c[0]), "+f"(c[1]), "+f"(c[2]), "+f"(c[3])
        : "r"(a[0]), "r"(a[1]), "r"(a[2]), "r"(a[3]), "r"(b0), "r"(b1));
}

#define LDSM_X4(r0, r1, r2, r3, addr) \
    asm volatile("ldmatrix.sync.aligned.m8n8.x4.shared.b16 {%0,%1,%2,%3}, [%4];" \
        : "=r"(r0), "=r"(r1), "=r"(r2), "=r"(r3) : "r"(addr))

// ---------------- K0: zero scratch ------------------------------------------
__global__ void k_zero() {
    int i = blockIdx.x * blockDim.x + threadIdx.x;
    if (i < kTOTV * 4) ((float*)g_sums)[i] = 0.f;
    if (i < kTOTV) { g_counts[i] = 0.f; g_cursor[i] = 0; }
}

// ---------------- K1: segment sums + counts (all 4 scales) ------------------
__global__ void k_accum(const float4* __restrict__ pts, const int* __restrict__ pvs) {
    int p = blockIdx.x * blockDim.x + threadIdx.x;
    if (p >= NPTS) return;
    float4 q = pts[p];
    const int off[4] = {kOFF0, kOFF1, kOFF2, kOFF3};
#pragma unroll
    for (int i = 0; i < 4; i++) {
        int b = off[i] + pvs[i * NPTS + p];
        atomicAdd(&g_sums[b].x, q.x);
        atomicAdd(&g_sums[b].y, q.y);
        atomicAdd(&g_sums[b].z, q.z);
        atomicAdd(&g_sums[b].w, q.w);
        atomicAdd(&g_counts[b], 1.f);
    }
}

// ---------------- K2: per-scale exclusive scan of counts -> offsets ---------
__global__ void k_scan() {
    __shared__ int sh[1024];
    const int Vs[4]  = {kV0, kV1, kV2, kV3};
    const int off[4] = {kOFF0, kOFF1, kOFF2, kOFF3};
    int s = blockIdx.x;
    int V = Vs[s], base = off[s];
    int chunk = (V + 1023) / 1024;
    int lo = threadIdx.x * chunk;
    int hi = min(lo + chunk, V);
    int sum = 0;
    for (int v = lo; v < hi; v++) sum += (int)g_counts[base + v];
    sh[threadIdx.x] = sum;
    __syncthreads();
    if (threadIdx.x == 0) {
        int run = 0;
        for (int t = 0; t < 1024; t++) { int x = sh[t]; sh[t] = run; run += x; }
    }
    __syncthreads();
    int run = sh[threadIdx.x];
    for (int v = lo; v < hi; v++) { g_offsets[base + v] = run; run += (int)g_counts[base + v]; }
}

// ---------------- K3: fill CSR point lists ----------------------------------
__global__ void k_fill(const int* __restrict__ pvs) {
    int p = blockIdx.x * blockDim.x + threadIdx.x;
    if (p >= NPTS) return;
    const int off[4] = {kOFF0, kOFF1, kOFF2, kOFF3};
#pragma unroll
    for (int i = 0; i < 4; i++) {
        int b = off[i] + pvs[i * NPTS + p];
        int pos = atomicAdd(&g_cursor[b], 1);
        g_plist[i * NPTS + g_offsets[b] + pos] = p;
    }
}

// ---------------- K3b: transpose W_pt2 -> [n][k] half -----------------------
__global__ void k_prepw(const float* __restrict__ Wpt2) {
    int idx = blockIdx.x * blockDim.x + threadIdx.x;
    if (idx >= 128 * 384) return;
    int n = idx / 384, k = idx % 384;
    g_wt[idx] = __float2half(Wpt2[k * 128 + n]);
}

// ---------------- K4: AVFE point stage (3 scales), warp per point -----------
__global__ __launch_bounds__(256) void k_avfe1(
    const float4* __restrict__ pts, const float* __restrict__ Wp1,
    const float* __restrict__ Wa1, const int* __restrict__ pvs) {
    __shared__ float sWp[256];   // [4][64]
    __shared__ float sWa[512];   // [8][64]
    for (int j = threadIdx.x; j < 256; j += 256) sWp[j] = Wp1[j];
    for (int j = threadIdx.x; j < 512; j += 256) sWa[j] = Wa1[j];
    __syncthreads();

    int w = blockIdx.x * 8 + (threadIdx.x >> 5);
    if (w >= NPTS) return;
    int lane = threadIdx.x & 31;
    int c0 = lane, c1 = lane + 32;
    float4 q = pts[w];
    float pf0 = relu(q.x * sWp[c0] + q.y * sWp[64 + c0] + q.z * sWp[128 + c0] + q.w * sWp[192 + c0]);
    float pf1 = relu(q.x * sWp[c1] + q.y * sWp[64 + c1] + q.z * sWp[128 + c1] + q.w * sWp[192 + c1]);
    size_t fb = (size_t)w * 192;
    const int off[3] = {kOFF0, kOFF1, kOFF2};
#pragma unroll
    for (int i = 0; i < 3; i++) {
        int b = off[i] + pvs[i * NPTS + w];
        float inv = 1.0f / fmaxf(g_counts[b], 1.0f);
        float4 s = g_sums[b];
        float m0 = s.x * inv, m1 = s.y * inv, m2 = s.z * inv, m3 = s.w * inv;
        float a0 = q.x - m0, a1 = q.y - m1, a2 = q.z - m2, a3 = q.w;
        float af0 = a0 * sWa[c0] + a1 * sWa[64 + c0] + a2 * sWa[128 + c0] + a3 * sWa[192 + c0]
                  + m0 * sWa[256 + c0] + m1 * sWa[320 + c0] + m2 * sWa[384 + c0] + m3 * sWa[448 + c0];
        float af1 = a0 * sWa[c1] + a1 * sWa[64 + c1] + a2 * sWa[128 + c1] + a3 * sWa[192 + c1]
                  + m0 * sWa[256 + c1] + m1 * sWa[320 + c1] + m2 * sWa[384 + c1] + m3 * sWa[448 + c1];
        g_sf1[fb + i * 64 + c0] = __float2half(pf0 * relu(af0));
        g_sf1[fb + i * 64 + c1] = __float2half(pf1 * relu(af1));
    }
}

// ------ K5: segment-max (scales 0-2) -> g_vmax[V,64] ------------------------
__global__ __launch_bounds__(256) void k_max1() {
    int w = blockIdx.x * 8 + (threadIdx.x >> 5);
    if (w >= kVIN) return;
    int lane = threadIdx.x & 31;
    int i;
    if (w < kV0)            i = 0;
    else if (w < kV0 + kV1) i = 1;
    else                    i = 2;
    int b = w;                       // global voxel index, scales 0-2 packed
    int o = g_offsets[b];
    int cnt = (int)g_counts[b];
    const int* pl = &g_plist[i * NPTS + o];
    float m0 = 0.f, m1 = 0.f;        // sf >= 0 always (product of relus)
    for (int t = 0; t < cnt; t++) {
        int pt = pl[t];
        size_t fb = (size_t)pt * 192 + i * 64;
        m0 = fmaxf(m0, __half2float(g_sf1[fb + lane]));
        m1 = fmaxf(m1, __half2float(g_sf1[fb + lane + 32]));
    }
    g_vmax[(size_t)b * 64 + lane]      = __float2half(m0);
    g_vmax[(size_t)b * 64 + lane + 32] = __float2half(m1);
}

// ------ K6: HMMA GEMM  sf2 = relu(final@W_pt2) * relu(att2@W_att2) ----------
// Logical A[N,384]: per scale i: cols [i*128, i*128+64) = g_sf1, [.. +128) =
// g_vmax[voxel] gather. CTA: 128 rows x 128 cols, 8 warps as 4x2; warp tile
// 32 rows x 64 cols (2 m-tiles x 8 n-tiles). K in 12 chunks of 32, double-
// buffered smem with register staging; ldmatrix.x4 fragment loads.
static constexpr int GS = 40;   // smem row stride in halves (conflict-free)

__global__ __launch_bounds__(256, 2) void k_gemm_mma(
    const float4* __restrict__ pts, const float* __restrict__ Watt2,
    const int* __restrict__ pvs) {
    __shared__ __align__(16) __half sA[2][128 * GS];
    __shared__ __align__(16) __half sB[2][128 * GS];
    __shared__ float sWs[1024];
    __shared__ int   svox[3][128];

    int tid = threadIdx.x;
    int warp = tid >> 5, lane = tid & 31;
    int rg = warp >> 1, cg = warp & 1;   // row-group (0..3), col-group (0..1)
    int p0 = blockIdx.x * 128;

    for (int j = tid; j < 1024; j += 256) sWs[j] = Watt2[j];
    for (int j = tid; j < 384; j += 256) {
        int i = j >> 7, r = j & 127;
        int p = p0 + r;
        svox[i][r] = (p < NPTS) ? pvs[i * NPTS + p] : 0;
    }
    const int voff[3] = {kOFF0, kOFF1, kOFF2};

    float acc[2][8][4];
#pragma unroll
    for (int mt = 0; mt < 2; mt++)
#pragma unroll
        for (int nt = 0; nt < 8; nt++)
#pragma unroll
            for (int j = 0; j < 4; j++) acc[mt][nt][j] = 0.f;

    uint4 ra[2], rb[2];
    auto load_chunk = [&](int c) {
        int i_s = c >> 2, sub = c & 3;
#pragma unroll
        for (int it = 0; it < 2; it++) {
            int idx = it * 256 + tid;
            int row = idx >> 2, seg = idx & 3;
            int p = p0 + row;
            uint4 v = {0, 0, 0, 0};
            if (sub < 2) {
                if (p < NPTS)
                    v = *(const uint4*)&g_sf1[(size_t)p * 192 + i_s * 64 + sub * 32 + seg * 8];
            } else {
                int vox = svox[i_s][row];
                v = *(const uint4*)&g_vmax[((size_t)(voff[i_s] + vox)) * 64 + (sub - 2) * 32 + seg * 8];
            }
            ra[it] = v;
            rb[it] = *(const uint4*)&g_wt[row * 384 + c * 32 + seg * 8];
        }
    };
    auto store_chunk = [&](int buf) {
#pragma unroll
        for (int it = 0; it < 2; it++) {
            int idx = it * 256 + tid;
            int row = idx >> 2, seg = idx & 3;
            *(uint4*)&sA[buf][row * GS + seg * 8] = ra[it];
            *(uint4*)&sB[buf][row * GS + seg * 8] = rb[it];
        }
    };

    int g = lane >> 3, rit = lane & 7;
    // lane-dependent ldmatrix address offsets (in halves)
    int a_row_l = rit + (g & 1) * 8;       // within 16-row tile
    int a_col_l = (g >> 1) * 8;
    int b_row_l = rit + (g >> 1) * 8;      // within 16-row pair
    int b_col_l = (g & 1) * 8;

    load_chunk(0);
    for (int c = 0; c < 12; c++) {
        int buf = c & 1;
        store_chunk(buf);
        __syncthreads();
        if (c < 11) load_chunk(c + 1);
        uint32_t sa_b = smem_u32(&sA[buf][0]);
        uint32_t sb_b = smem_u32(&sB[buf][0]);
#pragma unroll
        for (int ks = 0; ks < 2; ks++) {
            uint32_t a[2][4];
#pragma unroll
            for (int mt = 0; mt < 2; mt++) {
                uint32_t addr = sa_b + (((rg * 32 + mt * 16 + a_row_l) * GS) + ks * 16 + a_col_l) * 2;
                LDSM_X4(a[mt][0], a[mt][1], a[mt][2], a[mt][3], addr);
            }
#pragma unroll
            for (int bp = 0; bp < 4; bp++) {
                uint32_t b0a, b1a, b0b, b1b;
                uint32_t addr = sb_b + (((cg * 64 + bp * 16 + b_row_l) * GS) + ks * 16 + b_col_l) * 2;
                LDSM_X4(b0a, b1a, b0b, b1b, addr);
                mma16816(acc[0][2 * bp], a[0], b0a, b1a);
                mma16816(acc[0][2 * bp + 1], a[0], b0b, b1b);
                mma16816(acc[1][2 * bp], a[1], b0a, b1a);
                mma16816(acc[1][2 * bp + 1], a[1], b0b, b1b);
            }
        }
        __syncthreads();
    }

    // Epilogue: attention-2 + relu + sf2 write
#pragma unroll
    for (int mt = 0; mt < 2; mt++) {
#pragma unroll
        for (int rsel = 0; rsel < 2; rsel++) {
            int p = p0 + rg * 32 + mt * 16 + rsel * 8 + (lane >> 2);
            if (p >= NPTS) continue;
            int b = kOFF3 + pvs[3 * NPTS + p];
            float inv = 1.0f / fmaxf(g_counts[b], 1.0f);
            float4 s = g_sums[b];
            float4 q = pts[p];
            float m0 = s.x * inv, m1 = s.y * inv, m2 = s.z * inv, m3 = s.w * inv;
            float a0 = q.x - m0, a1 = q.y - m1, a2 = q.z - m2, a3 = q.w;
#pragma unroll
            for (int nt = 0; nt < 8; nt++) {
                int c = cg * 64 + nt * 8 + 2 * (lane & 3);
                float af0 = a0 * sWs[c] + a1 * sWs[128 + c] + a2 * sWs[256 + c]
                          + a3 * sWs[384 + c] + m0 * sWs[512 + c] + m1 * sWs[640 + c]
                          + m2 * sWs[768 + c] + m3 * sWs[896 + c];
                int c1 = c + 1;
                float af1 = a0 * sWs[c1] + a1 * sWs[128 + c1] + a2 * sWs[256 + c1]
                          + a3 * sWs[384 + c1] + m0 * sWs[512 + c1] + m1 * sWs[640 + c1]
                          + m2 * sWs[768 + c1] + m3 * sWs[896 + c1];
                float2 o;
                o.x = relu(acc[mt][nt][rsel * 2 + 0]) * relu(af0);
                o.y = relu(acc[mt][nt][rsel * 2 + 1]) * relu(af1);
                *(float2*)&g_sf2[(size_t)p * 128 + c] = o;
            }
        }
    }
}

// ------ K7: segment-max over sf2 (scale 3) + scatter into dense output ------
__global__ __launch_bounds__(256) void k_maxout(
    const int* __restrict__ vfs, float* __restrict__ out) {
    int w = blockIdx.x * 8 + (threadIdx.x >> 5);
    if (w >= kV3) return;
    int lane = threadIdx.x & 31;
    int b = kOFF3 + w;
    int o = g_offsets[b];
    int cnt = (int)g_counts[b];
    const int* pl = &g_plist[3 * NPTS + o];
    float m0 = 0.f, m1 = 0.f, m2 = 0.f, m3 = 0.f;
    for (int t = 0; t < cnt; t++) {
        int pt = pl[t];
        size_t sb = (size_t)pt * 128 + lane;
        m0 = fmaxf(m0, g_sf2[sb]);
        m1 = fmaxf(m1, g_sf2[sb + 32]);
        m2 = fmaxf(m2, g_sf2[sb + 64]);
        m3 = fmaxf(m3, g_sf2[sb + 96]);
    }
    int vb = vfs[w * 3 + 0], vy = vfs[w * 3 + 1], vx = vfs[w * 3 + 2];
    size_t ob = (size_t)vb * 128 * 262144 + (size_t)vy * 512 + vx;
    out[ob + (size_t)(lane)      * 262144] = m0;
    out[ob + (size_t)(lane + 32) * 262144] = m1;
    out[ob + (size_t)(lane + 64) * 262144] = m2;
    out[ob + (size_t)(lane + 96) * 262144] = m3;
}

// ---------------------------------------------------------------------------
extern "C" void kernel_launch(void* const* d_in, const int* in_sizes, int n_in,
                              void* d_out, int out_size) {
    const float4* pts   = (const float4*)d_in[0];
    const float*  Wp1   = (const float*)d_in[1];
    const float*  Wa1   = (const float*)d_in[2];
    const float*  Wpt2  = (const float*)d_in[3];
    const float*  Watt2 = (const float*)d_in[4];
    const int*    pvs   = (const int*)d_in[5];
    const int*    vfs   = (const int*)d_in[6];
    float*        out   = (float*)d_out;

    cudaMemsetAsync(d_out, 0, (size_t)out_size * sizeof(float), 0);

    k_zero<<<(kTOTV * 4 + 255) / 256, 256>>>();
    k_accum<<<(NPTS + 255) / 256, 256>>>(pts, pvs);
    k_scan<<<4, 1024>>>();
    k_fill<<<(NPTS + 255) / 256, 256>>>(pvs);
    k_prepw<<<(128 * 384 + 255) / 256, 256>>>(Wpt2);
    k_avfe1<<<(NPTS + 7) / 8, 256>>>(pts, Wp1, Wa1, pvs);
    k_max1<<<(kVIN + 7) / 8, 256>>>();
    k_gemm_mma<<<(NPTS + 127) / 128, 256>>>(pts, Watt2, pvs);
    k_maxout<<<(kV3 + 7) / 8, 256>>>(vfs, out);
}

// round 6
// speedup vs baseline: 1.0817x; 1.0817x over previous
#include <cuda_runtime.h>
#include <cuda_fp16.h>
#include <cstdint>
#include <cstddef>

#define NPTS 300000

static constexpr int kV0 = 60000, kV1 = 30000, kV2 = 15000, kV3 = 120000;
static constexpr int kTOTV = kV0 + kV1 + kV2 + kV3;            // 225000
static constexpr int kOFF0 = 0, kOFF1 = 60000, kOFF2 = 90000, kOFF3 = 105000;
static constexpr int kVIN = kV0 + kV1 + kV2;                   // 105000

// ---------------- scratch (static device globals; no allocation) -------------
__device__ float4 g_sums[kTOTV];            // per-voxel point sums (x,y,z,w)
__device__ float  g_counts[kTOTV];          // per-voxel counts
__device__ int    g_offsets[kTOTV];         // per-scale exclusive scan of counts
__device__ int    g_cursor[kTOTV];          // fill cursors
__device__ int    g_plist[4 * NPTS];        // CSR point lists, segmented per scale
__device__ __half g_sf1[(size_t)NPTS * 192];   // [N, 3*64] AVFE sf features (half)
__device__ __half g_vmax[(size_t)kVIN * 64];   // per-voxel max of sf, scales 0-2
__device__ __half g_sf2h[(size_t)NPTS * 128];  // [N,128] AVFEO sf (half)
__device__ __half g_wt[128 * 384];          // W_pt2 transposed to [n][k], half

__device__ __forceinline__ float relu(float x) { return fmaxf(x, 0.f); }

__device__ __forceinline__ void mma16816(float* c, uint32_t a0, uint32_t a1,
                                         uint32_t a2, uint32_t a3,
                                         uint32_t b0, uint32_t b1) {
    asm volatile(
        "mma.sync.aligned.m16n8k16.row.col.f32.f16.f16.f32 "
        "{%0,%1,%2,%3}, {%4,%5,%6,%7}, {%8,%9}, {%0,%1,%2,%3};"
        : "+f"(c[0]), "+f"(c[1]), "+f"(c[2]), "+f"(c[3])
        : "r"(a0), "r"(a1), "r"(a2), "r"(a3), "r"(b0), "r"(b1));
}

// ---------------- K0: zero scratch ------------------------------------------
__global__ void k_zero() {
    int i = blockIdx.x * blockDim.x + threadIdx.x;
    if (i < kTOTV * 4) ((float*)g_sums)[i] = 0.f;
    if (i < kTOTV) { g_counts[i] = 0.f; g_cursor[i] = 0; }
}

// ---------------- K1: segment sums + counts (all 4 scales) ------------------
__global__ void k_accum(const float4* __restrict__ pts, const int* __restrict__ pvs) {
    int p = blockIdx.x * blockDim.x + threadIdx.x;
    if (p >= NPTS) return;
    float4 q = pts[p];
    const int off[4] = {kOFF0, kOFF1, kOFF2, kOFF3};
#pragma unroll
    for (int i = 0; i < 4; i++) {
        int b = off[i] + pvs[i * NPTS + p];
        atomicAdd(&g_sums[b].x, q.x);
        atomicAdd(&g_sums[b].y, q.y);
        atomicAdd(&g_sums[b].z, q.z);
        atomicAdd(&g_sums[b].w, q.w);
        atomicAdd(&g_counts[b], 1.f);
    }
}

// ---------------- K2: per-scale exclusive scan of counts -> offsets ---------
__global__ void k_scan() {
    __shared__ int sh[1024];
    const int Vs[4]  = {kV0, kV1, kV2, kV3};
    const int off[4] = {kOFF0, kOFF1, kOFF2, kOFF3};
    int s = blockIdx.x;
    int V = Vs[s], base = off[s];
    int chunk = (V + 1023) / 1024;
    int lo = threadIdx.x * chunk;
    int hi = min(lo + chunk, V);
    int sum = 0;
    for (int v = lo; v < hi; v++) sum += (int)g_counts[base + v];
    sh[threadIdx.x] = sum;
    __syncthreads();
    if (threadIdx.x == 0) {
        int run = 0;
        for (int t = 0; t < 1024; t++) { int x = sh[t]; sh[t] = run; run += x; }
    }
    __syncthreads();
    int run = sh[threadIdx.x];
    for (int v = lo; v < hi; v++) { g_offsets[base + v] = run; run += (int)g_counts[base + v]; }
}

// ---------------- K3: fill CSR point lists ----------------------------------
__global__ void k_fill(const int* __restrict__ pvs) {
    int p = blockIdx.x * blockDim.x + threadIdx.x;
    if (p >= NPTS) return;
    const int off[4] = {kOFF0, kOFF1, kOFF2, kOFF3};
#pragma unroll
    for (int i = 0; i < 4; i++) {
        int b = off[i] + pvs[i * NPTS + p];
        int pos = atomicAdd(&g_cursor[b], 1);
        g_plist[i * NPTS + g_offsets[b] + pos] = p;
    }
}

// ---------------- K3b: transpose W_pt2 -> [n][k] half -----------------------
__global__ void k_prepw(const float* __restrict__ Wpt2) {
    int idx = blockIdx.x * blockDim.x + threadIdx.x;
    if (idx >= 128 * 384) return;
    int n = idx / 384, k = idx % 384;
    g_wt[idx] = __float2half(Wpt2[k * 128 + n]);
}

// ---------------- K4: AVFE point stage (3 scales), warp per point -----------
__global__ __launch_bounds__(256) void k_avfe1(
    const float4* __restrict__ pts, const float* __restrict__ Wp1,
    const float* __restrict__ Wa1, const int* __restrict__ pvs) {
    __shared__ float sWp[256];   // [4][64]
    __shared__ float sWa[512];   // [8][64]
    for (int j = threadIdx.x; j < 256; j += 256) sWp[j] = Wp1[j];
    for (int j = threadIdx.x; j < 512; j += 256) sWa[j] = Wa1[j];
    __syncthreads();

    int w = blockIdx.x * 8 + (threadIdx.x >> 5);
    if (w >= NPTS) return;
    int lane = threadIdx.x & 31;
    int c0 = lane, c1 = lane + 32;
    float4 q = pts[w];
    float pf0 = relu(q.x * sWp[c0] + q.y * sWp[64 + c0] + q.z * sWp[128 + c0] + q.w * sWp[192 + c0]);
    float pf1 = relu(q.x * sWp[c1] + q.y * sWp[64 + c1] + q.z * sWp[128 + c1] + q.w * sWp[192 + c1]);
    size_t fb = (size_t)w * 192;
    const int off[3] = {kOFF0, kOFF1, kOFF2};
#pragma unroll
    for (int i = 0; i < 3; i++) {
        int b = off[i] + pvs[i * NPTS + w];
        float inv = 1.0f / fmaxf(g_counts[b], 1.0f);
        float4 s = g_sums[b];
        float m0 = s.x * inv, m1 = s.y * inv, m2 = s.z * inv, m3 = s.w * inv;
        float a0 = q.x - m0, a1 = q.y - m1, a2 = q.z - m2, a3 = q.w;
        float af0 = a0 * sWa[c0] + a1 * sWa[64 + c0] + a2 * sWa[128 + c0] + a3 * sWa[192 + c0]
                  + m0 * sWa[256 + c0] + m1 * sWa[320 + c0] + m2 * sWa[384 + c0] + m3 * sWa[448 + c0];
        float af1 = a0 * sWa[c1] + a1 * sWa[64 + c1] + a2 * sWa[128 + c1] + a3 * sWa[192 + c1]
                  + m0 * sWa[256 + c1] + m1 * sWa[320 + c1] + m2 * sWa[384 + c1] + m3 * sWa[448 + c1];
        g_sf1[fb + i * 64 + c0] = __float2half(pf0 * relu(af0));
        g_sf1[fb + i * 64 + c1] = __float2half(pf1 * relu(af1));
    }
}

// ------ K5: segment-max (scales 0-2) -> g_vmax[V,64] (no gather-back) -------
__global__ __launch_bounds__(256) void k_max1() {
    int w = blockIdx.x * 8 + (threadIdx.x >> 5);
    if (w >= kVIN) return;
    int lane = threadIdx.x & 31;
    int i;
    if (w < kV0)            i = 0;
    else if (w < kV0 + kV1) i = 1;
    else                    i = 2;
    int b = w;                       // packed global voxel index, scales 0-2
    int o = g_offsets[b];
    int cnt = (int)g_counts[b];
    const int* pl = &g_plist[i * NPTS + o];
    float m0 = 0.f, m1 = 0.f;        // sf >= 0 always (product of relus)
    for (int t = 0; t < cnt; t++) {
        int pt = pl[t];
        size_t fb = (size_t)pt * 192 + i * 64;
        m0 = fmaxf(m0, __half2float(g_sf1[fb + lane]));
        m1 = fmaxf(m1, __half2float(g_sf1[fb + lane + 32]));
    }
    g_vmax[(size_t)b * 64 + lane]      = __float2half(m0);
    g_vmax[(size_t)b * 64 + lane + 32] = __float2half(m1);
}

// ------ K6: HMMA GEMM  sf2 = relu(final@W_pt2) * relu(att2@W_att2) ----------
// R3-proven structure: CTA 128 rows x N=128, 8 warps; warp 16 rows x 128 cols
// (16 n-tiles m16n8k16). K=384 in 12 chunks of 32; smem stride 40 halves.
// A-tile: chunks c (scale i=c>>2, sub=c&3): sub 0,1 -> g_sf1 stream;
// sub 2,3 -> g_vmax gather (13MB, L2-resident).
static constexpr int GSTRIDE = 40;

__global__ __launch_bounds__(256) void k_gemm_mma(
    const float4* __restrict__ pts, const float* __restrict__ Watt2,
    const int* __restrict__ pvs) {
    __shared__ __align__(16) __half sA[128 * GSTRIDE];
    __shared__ __align__(16) __half sB[128 * GSTRIDE];
    __shared__ float sWs[1024];
    __shared__ int   svox[3][128];

    int tid = threadIdx.x;
    int warp = tid >> 5, lane = tid & 31;
    int p0 = blockIdx.x * 128;
    for (int j = tid; j < 1024; j += 256) sWs[j] = Watt2[j];
    for (int j = tid; j < 384; j += 256) {
        int i = j >> 7, r = j & 127;
        int p = p0 + r;
        svox[i][r] = (p < NPTS) ? pvs[i * NPTS + p] : 0;
    }
    const int voff[3] = {kOFF0, kOFF1, kOFF2};

    float acc[16][4];
#pragma unroll
    for (int nt = 0; nt < 16; nt++)
#pragma unroll
        for (int j = 0; j < 4; j++) acc[nt][j] = 0.f;

    for (int c = 0; c < 12; c++) {
        int i_s = c >> 2, sub = c & 3;
#pragma unroll
        for (int it = 0; it < 2; it++) {
            int idx = it * 256 + tid;
            int row = idx >> 2, seg = idx & 3;
            int gp = p0 + row;
            uint4 av = {0, 0, 0, 0};
            if (sub < 2) {
                if (gp < NPTS)
                    av = *(const uint4*)&g_sf1[(size_t)gp * 192 + i_s * 64 + sub * 32 + seg * 8];
            } else {
                int vox = svox[i_s][row];
                av = *(const uint4*)&g_vmax[((size_t)(voff[i_s] + vox)) * 64 + (sub - 2) * 32 + seg * 8];
            }
            *(uint4*)&sA[row * GSTRIDE + seg * 8] = av;
            uint4 bv = *(const uint4*)&g_wt[row * 384 + c * 32 + seg * 8];
            *(uint4*)&sB[row * GSTRIDE + seg * 8] = bv;
        }
        __syncthreads();
#pragma unroll
        for (int ks = 0; ks < 2; ks++) {
            int ar = warp * 16 + (lane >> 2);
            int ac = ks * 16 + 2 * (lane & 3);
            uint32_t a0 = *(const uint32_t*)&sA[ar * GSTRIDE + ac];
            uint32_t a1 = *(const uint32_t*)&sA[(ar + 8) * GSTRIDE + ac];
            uint32_t a2 = *(const uint32_t*)&sA[ar * GSTRIDE + ac + 8];
            uint32_t a3 = *(const uint32_t*)&sA[(ar + 8) * GSTRIDE + ac + 8];
#pragma unroll
            for (int nt = 0; nt < 16; nt++) {
                int br = nt * 8 + (lane >> 2);
                int bc = ks * 16 + 2 * (lane & 3);
                uint32_t b0 = *(const uint32_t*)&sB[br * GSTRIDE + bc];
                uint32_t b1 = *(const uint32_t*)&sB[br * GSTRIDE + bc + 8];
                mma16816(acc[nt], a0, a1, a2, a3, b0, b1);
            }
        }
        __syncthreads();
    }

    // Epilogue: attention-2 + relu + half2 sf2 write
    int ra = p0 + warp * 16 + (lane >> 2);
    int rb = ra + 8;
#pragma unroll
    for (int rsel = 0; rsel < 2; rsel++) {
        int p = rsel ? rb : ra;
        if (p >= NPTS) continue;
        int b = kOFF3 + pvs[3 * NPTS + p];
        float inv = 1.0f / fmaxf(g_counts[b], 1.0f);
        float4 s = g_sums[b];
        float4 q = pts[p];
        float m0 = s.x * inv, m1 = s.y * inv, m2 = s.z * inv, m3 = s.w * inv;
        float a0 = q.x - m0, a1 = q.y - m1, a2 = q.z - m2, a3 = q.w;
#pragma unroll
        for (int nt = 0; nt < 16; nt++) {
            int c = nt * 8 + 2 * (lane & 3);
            float af0 = a0 * sWs[c] + a1 * sWs[128 + c] + a2 * sWs[256 + c]
                      + a3 * sWs[384 + c] + m0 * sWs[512 + c] + m1 * sWs[640 + c]
                      + m2 * sWs[768 + c] + m3 * sWs[896 + c];
            int c1 = c + 1;
            float af1 = a0 * sWs[c1] + a1 * sWs[128 + c1] + a2 * sWs[256 + c1]
                      + a3 * sWs[384 + c1] + m0 * sWs[512 + c1] + m1 * sWs[640 + c1]
                      + m2 * sWs[768 + c1] + m3 * sWs[896 + c1];
            float v0 = relu(acc[nt][rsel * 2 + 0]) * relu(af0);
            float v1 = relu(acc[nt][rsel * 2 + 1]) * relu(af1);
            *(__half2*)&g_sf2h[(size_t)p * 128 + c] = __floats2half2_rn(v0, v1);
        }
    }
}

// ------ K7: segment-max over sf2 (scale 3) + scatter into dense output ------
__global__ __launch_bounds__(256) void k_maxout(
    const int* __restrict__ vfs, float* __restrict__ out) {
    int w = blockIdx.x * 8 + (threadIdx.x >> 5);
    if (w >= kV3) return;
    int lane = threadIdx.x & 31;
    int b = kOFF3 + w;
    int o = g_offsets[b];
    int cnt = (int)g_counts[b];
    const int* pl = &g_plist[3 * NPTS + o];
    float m0 = 0.f, m1 = 0.f, m2 = 0.f, m3 = 0.f;
    for (int t = 0; t < cnt; t++) {
        int pt = pl[t];
        size_t sb = (size_t)pt * 128 + lane;
        m0 = fmaxf(m0, __half2float(g_sf2h[sb]));
        m1 = fmaxf(m1, __half2float(g_sf2h[sb + 32]));
        m2 = fmaxf(m2, __half2float(g_sf2h[sb + 64]));
        m3 = fmaxf(m3, __half2float(g_sf2h[sb + 96]));
    }
    int vb = vfs[w * 3 + 0], vy = vfs[w * 3 + 1], vx = vfs[w * 3 + 2];
    size_t ob = (size_t)vb * 128 * 262144 + (size_t)vy * 512 + vx;
    out[ob + (size_t)(lane)      * 262144] = m0;
    out[ob + (size_t)(lane + 32) * 262144] = m1;
    out[ob + (size_t)(lane + 64) * 262144] = m2;
    out[ob + (size_t)(lane + 96) * 262144] = m3;
}

// ---------------------------------------------------------------------------
extern "C" void kernel_launch(void* const* d_in, const int* in_sizes, int n_in,
                              void* d_out, int out_size) {
    const float4* pts   = (const float4*)d_in[0];
    const float*  Wp1   = (const float*)d_in[1];
    const float*  Wa1   = (const float*)d_in[2];
    const float*  Wpt2  = (const float*)d_in[3];
    const float*  Watt2 = (const float*)d_in[4];
    const int*    pvs   = (const int*)d_in[5];
    const int*    vfs   = (const int*)d_in[6];
    float*        out   = (float*)d_out;

    cudaMemsetAsync(d_out, 0, (size_t)out_size * sizeof(float), 0);

    k_zero<<<(kTOTV * 4 + 255) / 256, 256>>>();
    k_accum<<<(NPTS + 255) / 256, 256>>>(pts, pvs);
    k_scan<<<4, 1024>>>();
    k_fill<<<(NPTS + 255) / 256, 256>>>(pvs);
    k_prepw<<<(128 * 384 + 255) / 256, 256>>>(Wpt2);
    k_avfe1<<<(NPTS + 7) / 8, 256>>>(pts, Wp1, Wa1, pvs);
    k_max1<<<(kVIN + 7) / 8, 256>>>();
    k_gemm_mma<<<(NPTS + 127) / 128, 256>>>(pts, Watt2, pvs);
    k_maxout<<<(kV3 + 7) / 8, 256>>>(vfs, out);
}